// round 2
// baseline (speedup 1.0000x reference)
#include <cuda_runtime.h>

#define BATCH   8192
#define ROW_LEN 128
#define DIM     128

// Partial per-row losses; reduced by a second kernel (deterministic, no atomics).
__device__ float g_partials[BATCH];

__global__ __launch_bounds__(128, 8)
void node2vec_row_kernel(const void* __restrict__ rt_raw,
                         const float* __restrict__ X,
                         const int* __restrict__ m_ptr) {
    const int b    = blockIdx.x;
    const int tid  = threadIdx.x;   // 0..127
    const int lane = tid & 31;
    const int warp = tid >> 5;      // 0..3

    __shared__ float x0s[DIM];
    __shared__ float scores[ROW_LEN];
    __shared__ float red[128];

    const int* __restrict__ rt32 = (const int*)rt_raw;

    // Runtime dtype detection: int64 data (values < 2^31) has zero high words
    // at odd 32-bit positions; int32 data has random indices there.
    const bool is64 = (rt32[1] == 0) & (rt32[3] == 0) & (rt32[5] == 0) & (rt32[7] == 0);

    // Index fetch helper as lambda-free inline logic
    // row element l for batch b:
    //   int32: rt32[b*128 + l]
    //   int64: rt32[2*(b*128 + l)]   (low word)
    const long long base = (long long)b * ROW_LEN;

    // Load x0 = X[rt[b,0]] into shared (128 floats, one per thread)
    {
        const long long e0 = is64 ? (long long)rt32[2 * base] : (long long)rt32[base];
        x0s[tid] = __ldg(X + e0 * DIM + tid);
    }
    __syncthreads();

    // Each lane holds its float4 chunk of x0 in registers
    const float4 x0v = reinterpret_cast<const float4*>(x0s)[lane];

    // Each warp computes dot(X[rt[b,l]], x0) for l = warp, warp+4, ...
    #pragma unroll 4
    for (int l = warp; l < ROW_LEN; l += 4) {
        const long long pos = base + l;
        const long long idx = is64 ? (long long)rt32[2 * pos] : (long long)rt32[pos];
        const float4 v = __ldg(reinterpret_cast<const float4*>(X + idx * DIM) + lane);
        float d = v.x * x0v.x + v.y * x0v.y + v.z * x0v.z + v.w * x0v.w;
        #pragma unroll
        for (int off = 16; off > 0; off >>= 1)
            d += __shfl_xor_sync(0xffffffffu, d, off);
        if (lane == 0) scores[l] = d;
    }
    __syncthreads();

    const int m = m_ptr[0];         // low 32 bits = 20 for int32 or int64 (LE)
    const float s = scores[tid];

    // Block max
    red[tid] = s; __syncthreads();
    #pragma unroll
    for (int off = 64; off > 0; off >>= 1) {
        if (tid < off) red[tid] = fmaxf(red[tid], red[tid + off]);
        __syncthreads();
    }
    const float mx = red[0];
    __syncthreads();

    // Block sum of exp(s - mx)
    red[tid] = __expf(s - mx); __syncthreads();
    #pragma unroll
    for (int off = 64; off > 0; off >>= 1) {
        if (tid < off) red[tid] += red[tid + off];
        __syncthreads();
    }
    const float lse = mx + __logf(red[0]);
    __syncthreads();

    // pos = sum scores[1..m]
    red[tid] = (tid >= 1 && tid <= m) ? s : 0.0f;
    __syncthreads();
    #pragma unroll
    for (int off = 64; off > 0; off >>= 1) {
        if (tid < off) red[tid] += red[tid + off];
        __syncthreads();
    }

    if (tid == 0) g_partials[b] = (float)m * lse - red[0];
}

__global__ __launch_bounds__(256)
void node2vec_reduce_kernel(float* __restrict__ out) {
    __shared__ float red[256];
    const int tid = threadIdx.x;
    float s = 0.0f;
    for (int i = tid; i < BATCH; i += 256) s += g_partials[i];
    red[tid] = s; __syncthreads();
    #pragma unroll
    for (int off = 128; off > 0; off >>= 1) {
        if (tid < off) red[tid] += red[tid + off];
        __syncthreads();
    }
    if (tid == 0) out[0] = red[0] * (1.0f / (float)BATCH);
}

extern "C" void kernel_launch(void* const* d_in, const int* in_sizes, int n_in,
                              void* d_out, int out_size) {
    const void*  rt = d_in[0];                 // rt_batch [8192,128] int32 or int64
    const float* X  = (const float*)d_in[1];   // X float32 [100000,128]
    const int*   m  = (const int*)d_in[2];     // m scalar
    float* out = (float*)d_out;

    node2vec_row_kernel<<<BATCH, 128>>>(rt, X, m);
    node2vec_reduce_kernel<<<1, 256>>>(out);
}